// round 15
// baseline (speedup 1.0000x reference)
#include <cuda_runtime.h>
#include <cuda_fp16.h>
#include <cstdint>
#include <math.h>

// ---------------------------------------------------------------------------
// Problem constants
// ---------------------------------------------------------------------------
namespace {
constexpr int N_Q   = 20000;
constexpr int S_SUP = 20000;
constexpr int NEI   = 30;
constexpr int KP    = 15;
constexpr int CIN_  = 128;
constexpr int COUT_ = 256;
constexpr float INV_EXT = 20.0f;

constexpr int M_PAD = 20096;        // 157*128

// Extended-K layout: per k: 4 q-groups of 72 slots
constexpr int QW    = 72;
constexpr int KROW  = 4 * QW;             // 288
constexpr int BIGK2 = KP * KROW;          // 4320

// stage1 smem strides (halfs)
constexpr int LDF   = 296;   // f_h row stride: conflict-free
constexpr int LDW   = 40;    // w_h row stride
constexpr int LDO   = 292;   // out_sm row stride: conflict-free

// GEMM tiling
constexpr int BM = 128, BN = 128, BK = 48;
constexpr int NKC = BIGK2 / BK;           // 90
constexpr int LDS_ = 56;                  // smem row stride (fp16 elems)
constexpr int MAT_BYTES = 128 * LDS_ * 2; // 14336
constexpr int BUF_BYTES = 2 * MAT_BYTES;  // A|B = 28672
constexpr int NSTAGE = 4;                 // 4 stages, prefetch distance 3,
                                          // loads issued AFTER the barrier
constexpr int SMEM_DYN  = NSTAGE * BUF_BYTES;  // 114688
}

// ---------------------------------------------------------------------------
// Scratch (device globals, zero-initialized; pad rows never written)
// ---------------------------------------------------------------------------
__device__ __half g_A[(size_t)M_PAD * BIGK2];
__device__ __half g_B[(size_t)COUT_ * BIGK2];   // [co][kidx]
__device__ __half g_xh[(size_t)S_SUP * CIN_];   // x pre-converted to fp16

// ---------------------------------------------------------------------------
// PTX helpers (sm_80+/sm_100-family baseline; legal on family target)
// ---------------------------------------------------------------------------
__device__ __forceinline__ uint32_t smem_u32(const void* p) {
    uint32_t a;
    asm("{ .reg .u64 t; cvta.to.shared.u64 t, %1; cvt.u32.u64 %0, t; }"
        : "=r"(a) : "l"(p));
    return a;
}
__device__ __forceinline__ void cp16(uint32_t s, const void* g) {
    asm volatile("cp.async.cg.shared.global [%0], [%1], 16;" :: "r"(s), "l"(g));
}
__device__ __forceinline__ void cp16z(uint32_t s, const void* g, bool v) {
    const int sz = v ? 16 : 0;
    asm volatile("cp.async.cg.shared.global [%0], [%1], 16, %2;"
                 :: "r"(s), "l"(g), "r"(sz));
}
__device__ __forceinline__ void cp4z(uint32_t s, const void* g, bool v) {
    const int sz = v ? 4 : 0;
    asm volatile("cp.async.ca.shared.global [%0], [%1], 4, %2;"
                 :: "r"(s), "l"(g), "r"(sz));
}
__device__ __forceinline__ void cp_commit() {
    asm volatile("cp.async.commit_group;");
}
__device__ __forceinline__ void cp_wait2() {
    asm volatile("cp.async.wait_group 2;" ::: "memory");
}
__device__ __forceinline__ void cp_wait1() {
    asm volatile("cp.async.wait_group 1;" ::: "memory");
}
__device__ __forceinline__ void cp_wait0() {
    asm volatile("cp.async.wait_group 0;" ::: "memory");
}
__device__ __forceinline__ void ldmx4(uint32_t addr, uint32_t* r) {
    asm volatile("ldmatrix.sync.aligned.m8n8.x4.shared.b16 {%0,%1,%2,%3}, [%4];"
                 : "=r"(r[0]), "=r"(r[1]), "=r"(r[2]), "=r"(r[3]) : "r"(addr));
}
__device__ __forceinline__ void ldmx4t(uint32_t addr, uint32_t* r) {
    asm volatile("ldmatrix.sync.aligned.m8n8.x4.trans.shared.b16 {%0,%1,%2,%3}, [%4];"
                 : "=r"(r[0]), "=r"(r[1]), "=r"(r[2]), "=r"(r[3]) : "r"(addr));
}
__device__ __forceinline__ void ldmx2t(uint32_t addr, uint32_t* r) {
    asm volatile("ldmatrix.sync.aligned.m8n8.x2.trans.shared.b16 {%0,%1}, [%2];"
                 : "=r"(r[0]), "=r"(r[1]) : "r"(addr));
}
__device__ __forceinline__ void mma16816h(float* c, const uint32_t* a,
                                          uint32_t b0, uint32_t b1) {
    asm volatile(
        "mma.sync.aligned.m16n8k16.row.col.f32.f16.f16.f32 "
        "{%0,%1,%2,%3}, {%4,%5,%6,%7}, {%8,%9}, {%0,%1,%2,%3};"
        : "+f"(c[0]), "+f"(c[1]), "+f"(c[2]), "+f"(c[3])
        : "r"(a[0]), "r"(a[1]), "r"(a[2]), "r"(a[3]), "r"(b0), "r"(b1));
}
__device__ __forceinline__ float sqrt_approx(float x) {
    float y;
    asm("sqrt.approx.f32 %0, %1;" : "=f"(y) : "f"(x));
    return y;
}
__device__ __forceinline__ uint32_t h2pack(float a, float b) {
    const __half2 h = __floats2half2_rn(a, b);
    return *reinterpret_cast<const uint32_t*>(&h);
}

// ---------------------------------------------------------------------------
// x -> fp16 pre-convert
// ---------------------------------------------------------------------------
__global__ __launch_bounds__(256) void xhalf_kernel(const float* __restrict__ x) {
    const size_t i = (size_t)blockIdx.x * 1024 + threadIdx.x * 4;
    const float4 v = *reinterpret_cast<const float4*>(x + i);
    uint2 pk;
    pk.x = h2pack(v.x, v.y);
    pk.y = h2pack(v.z, v.w);
    *reinterpret_cast<uint2*>(&g_xh[i]) = pk;
}

// ---------------------------------------------------------------------------
// B prep: g_B[co][k*288+q*72+j] from weights/W_lrf/b_lrf.
// ---------------------------------------------------------------------------
__global__ __launch_bounds__(128) void bprep_kernel(
    const float* __restrict__ W,       // [15][256][256]
    const float* __restrict__ W_lrf,   // [36][32]
    const float* __restrict__ b_lrf)   // [32]
{
    extern __shared__ float s[];       // [64][256]
    __shared__ float Wl[36 * 32];
    __shared__ float bl[32];

    const int k   = blockIdx.x;
    const int q   = blockIdx.y;
    const int co  = blockIdx.z * 128 + threadIdx.x;
    const int tid = threadIdx.x;

    for (int i = tid; i < 36 * 32; i += 128) Wl[i] = W_lrf[i];
    if (tid < 32) bl[tid] = b_lrf[tid];

    const float* Wb = W + ((size_t)k * 256 + q * 64) * 256;
    for (int i = tid; i < 64 * 256 / 4; i += 128) {
        reinterpret_cast<float4*>(s)[i] =
            reinterpret_cast<const float4*>(Wb)[i];
    }
    __syncthreads();

    float acc[37];
    #pragma unroll
    for (int t = 0; t < 37; t++) acc[t] = 0.0f;

    #pragma unroll 4
    for (int c = 0; c < 32; c++) {
        const float sv = s[(32 + c) * 256 + co];
        #pragma unroll
        for (int t = 0; t < 36; t++) acc[t] += Wl[t * 32 + c] * sv;
        acc[36] += bl[c] * sv;
    }

    __half h[72];
    #pragma unroll
    for (int j = 0; j < 32; j++) h[j] = __float2half_rn(s[j * 256 + co]);
    #pragma unroll
    for (int t = 0; t < 37; t++) h[32 + t] = __float2half_rn(acc[t]);
    h[69] = __float2half_rn(0.f); h[70] = h[69]; h[71] = h[69];

    __half* dst = &g_B[(size_t)co * BIGK2 + k * KROW + q * QW];
    #pragma unroll
    for (int v = 0; v < 9; v++)
        reinterpret_cast<uint4*>(dst)[v] = reinterpret_cast<const uint4*>(h)[v];
}

// ---------------------------------------------------------------------------
// Stage 1: fp16 cp.async gather + geometry + tensor-core neighbor reduction.
// ---------------------------------------------------------------------------
__global__ __launch_bounds__(128) void stage1_kernel(
    const float* __restrict__ q_pts,
    const float* __restrict__ s_pts,
    const int*   __restrict__ neighb_inds,
    const float* __restrict__ q_lrf,
    const float* __restrict__ s_lrf,
    const float* __restrict__ kpts)
{
    __shared__ __align__(16) __half f_h[32 * LDF];      // 18944 B
    __shared__ __align__(16) __half w_h[4 * 16 * LDW];  // 5120 B
    __shared__ __align__(16) __half out_sm[15 * LDO];   // 8760 B
    __shared__ __align__(16) float  slrf_sm[30 * 36];   // 4320 B
    __shared__ __align__(16) float  spts_sm[30 * 4];
    __shared__ float ql[36];
    __shared__ float kp_s[48];
    __shared__ int   ind_s[30];
    __shared__ float qp[3];

    const int n    = blockIdx.x;
    const int tid  = threadIdx.x;
    const int wid  = tid >> 5;
    const int lane = tid & 31;

    if (tid < 36) ql[tid]    = q_lrf[(size_t)n * 36 + tid];
    if (tid < 45) kp_s[tid]  = kpts[tid];
    if (tid < 3)  qp[tid]    = q_pts[(size_t)n * 3 + tid];
    if (tid < 30) ind_s[tid] = neighb_inds[(size_t)n * NEI + tid];
    __syncthreads();   // ind_s ready

    const uint32_t slb = smem_u32(slrf_sm);
    const uint32_t spb = smem_u32(spts_sm);
    const uint32_t fba = smem_u32(f_h);
    const uint32_t wba = smem_u32(w_h);

    // ---- async gather: xh rows -> f_h[m][q*72 + c] fp16 (480 x 16B) ----
    #pragma unroll
    for (int it = 0; it < 4; it++) {
        const int i = tid + it * 128;
        if (i < 480) {
            const int m   = i >> 4;
            const int q   = (i >> 2) & 3;
            const int c8  = i & 3;
            const int ind = ind_s[m];
            const bool v  = (ind < S_SUP);
            cp16z(fba + (m * LDF + q * QW + c8 * 8) * 2,
                  g_xh + (size_t)(v ? ind : 0) * CIN_ + q * 32 + c8 * 8, v);
        }
    }
    // ---- async gather: s_lrf rows (270 x 16B) ----
    #pragma unroll
    for (int it = 0; it < 3; it++) {
        const int i = tid + it * 128;
        if (i < 270) {
            const int m = i / 9, t = i % 9;
            const int ind = ind_s[m];
            const bool v  = (ind < S_SUP);
            cp16z(slb + (m * 36 + t * 4) * 4,
                  s_lrf + (size_t)(v ? ind : 0) * 36 + t * 4, v);
        }
    }
    // ---- async gather: s_pts (3 x 4B per m) ----
    if (tid < 90) {
        const int m = tid / 3, e = tid % 3;
        const int ind = ind_s[m];
        const bool v  = (ind < S_SUP);
        cp4z(spb + (m * 4 + e) * 4, s_pts + (size_t)(v ? ind : 0) * 3 + e, v);
    }
    cp_commit();

    // ---- zero w_h and f_h pad rows while copies fly ----
    {
        uint4 z = make_uint4(0, 0, 0, 0);
        uint4* wz = reinterpret_cast<uint4*>(w_h);
        #pragma unroll
        for (int i = tid; i < 320; i += 128) wz[i] = z;
        uint4* fz = reinterpret_cast<uint4*>(f_h + 30 * LDF);
        if (tid < 74) fz[tid] = z;
    }
    cp_wait0();
    __syncthreads();

    // ---- per-(m,q) geometry -> w_h fp16 + f_h LRF channels fp16 ----
    if (tid < 120) {
        const int m = tid >> 2;
        const int q = tid & 3;
        const int ind = ind_s[m];
        const bool valid = (ind < S_SUP);
        const float* qlr = &ql[q * 9];

        const float nb0 = spts_sm[m * 4 + 0] - qp[0];
        const float nb1 = spts_sm[m * 4 + 1] - qp[1];
        const float nb2 = spts_sm[m * 4 + 2] - qp[2];
        const float a0 = nb0 * qlr[0] + nb1 * qlr[3] + nb2 * qlr[6];
        const float a1 = nb0 * qlr[1] + nb1 * qlr[4] + nb2 * qlr[7];
        const float a2 = nb0 * qlr[2] + nb1 * qlr[5] + nb2 * qlr[8];

        #pragma unroll
        for (int k = 0; k < KP; k++) {
            const float d0 = a0 - kp_s[k * 3 + 0];
            const float d1 = a1 - kp_s[k * 3 + 1];
            const float d2 = a2 - kp_s[k * 3 + 2];
            const float sq = d0 * d0 + d1 * d1 + d2 * d2;
            float w = 1.0f - sqrt_approx(sq) * INV_EXT;
            w = fmaxf(w, 0.0f);
            w_h[q * (16 * LDW) + k * LDW + m] = __float2half_rn(valid ? w : 0.0f);
        }

        float sl[36];
        {
            const float4* p = reinterpret_cast<const float4*>(&slrf_sm[m * 36]);
            #pragma unroll
            for (int t = 0; t < 9; t++) {
                const float4 v = p[t];
                sl[t * 4 + 0] = v.x; sl[t * 4 + 1] = v.y;
                sl[t * 4 + 2] = v.z; sl[t * 4 + 3] = v.w;
            }
        }
        float alv[36];
        #pragma unroll
        for (int s = 0; s < 4; s++)
            #pragma unroll
            for (int i = 0; i < 3; i++)
                #pragma unroll
                for (int j = 0; j < 3; j++) {
                    alv[s * 9 + i * 3 + j] =
                        qlr[0 * 3 + i] * sl[s * 9 + 0 * 3 + j] +
                        qlr[1 * 3 + i] * sl[s * 9 + 1 * 3 + j] +
                        qlr[2 * 3 + i] * sl[s * 9 + 2 * 3 + j];
                }
        uint32_t pk[20];
        #pragma unroll
        for (int i = 0; i < 18; i++) pk[i] = h2pack(alv[2 * i], alv[2 * i + 1]);
        pk[18] = h2pack(valid ? 1.0f : 0.0f, 0.0f);
        pk[19] = 0u;
        uint4* dst = reinterpret_cast<uint4*>(&f_h[m * LDF + q * QW + 32]);
        #pragma unroll
        for (int v = 0; v < 5; v++) {
            uint4 u;
            u.x = pk[4 * v + 0]; u.y = pk[4 * v + 1];
            u.z = pk[4 * v + 2]; u.w = pk[4 * v + 3];
            dst[v] = u;
        }
    }
    __syncthreads();

    // ---- phase 2 (tensor cores): per warp q = wid ----
    {
        const int q = wid;
        float c[9][4];
        #pragma unroll
        for (int t = 0; t < 9; t++)
            #pragma unroll
            for (int e = 0; e < 4; e++) c[t][e] = 0.0f;

        const uint32_t wb = wba + q * (16 * LDW) * 2;
        const int a_row = lane & 15;
        const int a_kof = (lane >> 4) * 8;
        const int b_row = (lane & 7) + ((lane >> 3) & 1) * 8;
        const int b_col = (lane >> 4) * 8;

        #pragma unroll
        for (int ks = 0; ks < 2; ks++) {
            const int k16 = ks * 16;
            uint32_t a[4];
            ldmx4(wb + (a_row * LDW + k16 + a_kof) * 2, a);

            uint32_t b[9][2];
            #pragma unroll
            for (int t = 0; t < 4; t++) {
                uint32_t r[4];
                ldmx4t(fba + ((k16 + b_row) * LDF + q * QW + t * 16 + b_col) * 2, r);
                b[2 * t + 0][0] = r[0]; b[2 * t + 0][1] = r[1];
                b[2 * t + 1][0] = r[2]; b[2 * t + 1][1] = r[3];
            }
            {
                uint32_t r[2];
                ldmx2t(fba + ((k16 + (lane & 15)) * LDF + q * QW + 64) * 2, r);
                b[8][0] = r[0]; b[8][1] = r[1];
            }

            #pragma unroll
            for (int t = 0; t < 9; t++)
                mma16816h(c[t], a, b[t][0], b[t][1]);
        }

        // ---- stage to out_sm [k][LDO], mask k=15 ----
        const int r1 = lane >> 2;
        const int jc = (lane & 3) * 2;
        __half* base = out_sm + r1 * LDO + q * QW + jc;
        #pragma unroll
        for (int t = 0; t < 9; t++) {
            const __half2 lo = __floats2half2_rn(c[t][0], c[t][1]);
            *reinterpret_cast<__half2*>(base + t * 8) = lo;
        }
        if (r1 < 7) {
            __half* base2 = base + 8 * LDO;
            #pragma unroll
            for (int t = 0; t < 9; t++) {
                const __half2 hi = __floats2half2_rn(c[t][2], c[t][3]);
                *reinterpret_cast<__half2*>(base2 + t * 8) = hi;
            }
        }
    }
    __syncthreads();

    // ---- coalesced copy out_sm -> g_A (1080 x uint2) ----
    {
        __half* dst = g_A + (size_t)n * BIGK2;
        #pragma unroll 3
        for (int i = tid; i < 15 * 72; i += 128) {
            const int k  = i / 72;
            const int jj = i % 72;
            const uint2 v = *reinterpret_cast<const uint2*>(&out_sm[k * LDO + jj * 4]);
            *reinterpret_cast<uint2*>(dst + k * KROW + jj * 4) = v;
        }
    }
}

// ---------------------------------------------------------------------------
// Stage 2: fp16 mma.sync GEMM. CTA 128x128, BK=48, 4 warps (64x64 tiles),
// 4-stage cp.async pipeline with prefetch distance 3; loads issued AFTER the
// per-chunk barrier (writer buffer (c+3)%4 == (c-1)%4, whose last readers
// finished compute(c-1) before barrier(c) -> race-free with ONE barrier).
// ---------------------------------------------------------------------------
__global__ __launch_bounds__(128)
void gemm_mma_kernel(const float* __restrict__ bias, float* __restrict__ C)
{
    extern __shared__ __align__(16) char sm[];
    const uint32_t s0 = smem_u32(sm);

    const int tid  = threadIdx.x;
    const int wid  = tid >> 5;
    const int lane = tid & 31;
    const int r0   = blockIdx.y * BM;
    const int c0   = blockIdx.x * BN;

    const int wm = (wid & 1) * 64;
    const int wn = (wid >> 1) * 64;

    float acc[4][8][4];
    #pragma unroll
    for (int i = 0; i < 4; i++)
        #pragma unroll
        for (int j = 0; j < 8; j++)
            #pragma unroll
            for (int e = 0; e < 4; e++) acc[i][j][e] = 0.0f;

    auto load_chunk = [&](int c, int buf) {
        const int kc = c * BK;
        const uint32_t base = s0 + buf * BUF_BYTES;
        #pragma unroll
        for (int it = 0; it < 6; it++) {
            const int i   = tid + it * 128;          // 0..767
            const int row = i / 6;
            const int kq  = (i % 6) * 8;
            const uint32_t so = row * (LDS_ * 2) + kq * 2;
            cp16(base + so, &g_A[(size_t)(r0 + row) * BIGK2 + kc + kq]);
            cp16(base + MAT_BYTES + so, &g_B[(size_t)(c0 + row) * BIGK2 + kc + kq]);
        }
        cp_commit();
    };

    const int a_row = lane & 15;
    const int a_kof = (lane >> 4) * 8;
    const int b_nof = ((lane >> 4) * 8) + (lane & 7);
    const int b_kof = ((lane >> 3) & 1) * 8;

    load_chunk(0, 0);
    load_chunk(1, 1);
    load_chunk(2, 2);

    for (int c = 0; c < NKC; c++) {
        // ensure chunk c landed (pending <= remaining prefetched chunks)
        if (c + 1 >= NKC)      cp_wait0();
        else if (c + 2 >= NKC) cp_wait1();
        else                   cp_wait2();
        __syncthreads();     // single barrier per chunk

        // issue next load AFTER barrier: targets (c+3)&3 == (c-1)&3, whose
        // readers all finished compute(c-1) before this barrier.
        if (c + 3 < NKC) load_chunk(c + 3, (c + 3) & 3);

        const uint32_t bA = s0 + (c & 3) * BUF_BYTES;
        const uint32_t bB = bA + MAT_BYTES;

        #pragma unroll
        for (int ks = 0; ks < 3; ks++) {
            const int k16 = ks * 16;
            uint32_t aH[4][4], bH[8][2];

            #pragma unroll
            for (int mt = 0; mt < 4; mt++) {
                const uint32_t off =
                    (wm + mt * 16 + a_row) * (LDS_ * 2) + (k16 + a_kof) * 2;
                ldmx4(bA + off, aH[mt]);
            }
            #pragma unroll
            for (int np = 0; np < 4; np++) {
                const uint32_t off =
                    (wn + np * 16 + b_nof) * (LDS_ * 2) + (k16 + b_kof) * 2;
                uint32_t t[4];
                ldmx4(bB + off, t);
                bH[np * 2 + 0][0] = t[0]; bH[np * 2 + 0][1] = t[1];
                bH[np * 2 + 1][0] = t[2]; bH[np * 2 + 1][1] = t[3];
            }

            #pragma unroll
            for (int mt = 0; mt < 4; mt++)
                #pragma unroll
                for (int nt = 0; nt < 8; nt++)
                    mma16816h(acc[mt][nt], aH[mt], bH[nt][0], bH[nt][1]);
        }
    }

    const int erow = lane >> 2;
    const int ecol = (lane & 3) * 2;
    #pragma unroll
    for (int nt = 0; nt < 8; nt++) {
        const int col = c0 + wn + nt * 8 + ecol;
        const float b0 = bias[col], b1 = bias[col + 1];
        #pragma unroll
        for (int mt = 0; mt < 4; mt++) {
            #pragma unroll
            for (int h = 0; h < 2; h++) {
                const int row = r0 + wm + mt * 16 + erow + h * 8;
                if (row < N_Q) {
                    float v0 = acc[mt][nt][h * 2 + 0] + b0;
                    float v1 = acc[mt][nt][h * 2 + 1] + b1;
                    v0 = (v0 >= 0.f) ? v0 : 0.1f * v0;
                    v1 = (v1 >= 0.f) ? v1 : 0.1f * v1;
                    *reinterpret_cast<float2*>(&C[(size_t)row * COUT_ + col]) =
                        make_float2(v0, v1);
                }
            }
        }
    }
}

// ---------------------------------------------------------------------------
// Launch
// ---------------------------------------------------------------------------
extern "C" void kernel_launch(void* const* d_in, const int* in_sizes, int n_in,
                              void* d_out, int out_size) {
    const float* q_pts   = (const float*)d_in[0];
    const float* s_pts   = (const float*)d_in[1];
    const int*   inds    = (const int*)  d_in[2];
    const float* x       = (const float*)d_in[3];
    const float* q_lrf   = (const float*)d_in[4];
    const float* s_lrf   = (const float*)d_in[5];
    const float* kpts    = (const float*)d_in[6];
    const float* weights = (const float*)d_in[7];
    const float* W_lrf   = (const float*)d_in[8];
    const float* b_lrf   = (const float*)d_in[9];
    const float* bias    = (const float*)d_in[10];
    float* out = (float*)d_out;

    cudaFuncSetAttribute(bprep_kernel,
                         cudaFuncAttributeMaxDynamicSharedMemorySize, 65536);
    cudaFuncSetAttribute(gemm_mma_kernel,
                         cudaFuncAttributeMaxDynamicSharedMemorySize, SMEM_DYN);

    xhalf_kernel<<<(S_SUP * CIN_) / 1024, 256>>>(x);
    bprep_kernel<<<dim3(KP, 4, 2), 128, 65536>>>(weights, W_lrf, b_lrf);

    stage1_kernel<<<N_Q, 128>>>(q_pts, s_pts, inds, q_lrf, s_lrf, kpts);

    dim3 ggrid(COUT_ / BN, M_PAD / BM);
    gemm_mma_kernel<<<ggrid, 128, SMEM_DYN>>>(bias, out);
}

// round 16
// speedup vs baseline: 1.0521x; 1.0521x over previous
#include <cuda_runtime.h>
#include <cuda_fp16.h>
#include <cstdint>
#include <math.h>

// ---------------------------------------------------------------------------
// Problem constants
// ---------------------------------------------------------------------------
namespace {
constexpr int N_Q   = 20000;
constexpr int S_SUP = 20000;
constexpr int NEI   = 30;
constexpr int KP    = 15;
constexpr int CIN_  = 128;
constexpr int COUT_ = 256;
constexpr float INV_EXT = 20.0f;

constexpr int M_PAD = 20096;        // stage1 scratch rows (>= N_Q)

// Extended-K layout: per k: 4 q-groups of 72 slots
constexpr int QW    = 72;
constexpr int KROW  = 4 * QW;             // 288
constexpr int BIGK2 = KP * KROW;          // 4320

// stage1 smem strides (halfs)
constexpr int LDF   = 296;   // f_h row stride: conflict-free
constexpr int LDW   = 40;    // w_h row stride
constexpr int LDO   = 292;   // out_sm row stride: conflict-free

// GEMM tiling: BM=160 -> grid 125x2 = 250 CTAs <= 296 capacity = ONE wave
constexpr int BM = 160, BN = 128, BK = 48;
constexpr int NKC = BIGK2 / BK;           // 90
constexpr int LDS_ = 56;                  // smem row stride (fp16 elems)
constexpr int MATA_BYTES = BM * LDS_ * 2; // 17920
constexpr int MATB_BYTES = BN * LDS_ * 2; // 14336
constexpr int BUF_BYTES  = MATA_BYTES + MATB_BYTES;  // 32256
constexpr int NSTAGE = 3;
constexpr int SMEM_DYN  = NSTAGE * BUF_BYTES;        // 96768 -> 2 CTAs/SM
}

// ---------------------------------------------------------------------------
// Scratch (device globals, zero-initialized; pad rows never written)
// ---------------------------------------------------------------------------
__device__ __half g_A[(size_t)M_PAD * BIGK2];
__device__ __half g_B[(size_t)COUT_ * BIGK2];   // [co][kidx]
__device__ __half g_xh[(size_t)S_SUP * CIN_];   // x pre-converted to fp16

// ---------------------------------------------------------------------------
// PTX helpers (sm_80+/sm_100-family baseline; legal on family target)
// ---------------------------------------------------------------------------
__device__ __forceinline__ uint32_t smem_u32(const void* p) {
    uint32_t a;
    asm("{ .reg .u64 t; cvta.to.shared.u64 t, %1; cvt.u32.u64 %0, t; }"
        : "=r"(a) : "l"(p));
    return a;
}
__device__ __forceinline__ void cp16(uint32_t s, const void* g) {
    asm volatile("cp.async.cg.shared.global [%0], [%1], 16;" :: "r"(s), "l"(g));
}
__device__ __forceinline__ void cp16z(uint32_t s, const void* g, bool v) {
    const int sz = v ? 16 : 0;
    asm volatile("cp.async.cg.shared.global [%0], [%1], 16, %2;"
                 :: "r"(s), "l"(g), "r"(sz));
}
__device__ __forceinline__ void cp4z(uint32_t s, const void* g, bool v) {
    const int sz = v ? 4 : 0;
    asm volatile("cp.async.ca.shared.global [%0], [%1], 4, %2;"
                 :: "r"(s), "l"(g), "r"(sz));
}
__device__ __forceinline__ void cp_commit() {
    asm volatile("cp.async.commit_group;");
}
__device__ __forceinline__ void cp_wait2() {
    asm volatile("cp.async.wait_group 2;" ::: "memory");
}
__device__ __forceinline__ void cp_wait1() {
    asm volatile("cp.async.wait_group 1;" ::: "memory");
}
__device__ __forceinline__ void cp_wait0() {
    asm volatile("cp.async.wait_group 0;" ::: "memory");
}
__device__ __forceinline__ void ldmx4(uint32_t addr, uint32_t* r) {
    asm volatile("ldmatrix.sync.aligned.m8n8.x4.shared.b16 {%0,%1,%2,%3}, [%4];"
                 : "=r"(r[0]), "=r"(r[1]), "=r"(r[2]), "=r"(r[3]) : "r"(addr));
}
__device__ __forceinline__ void ldmx4t(uint32_t addr, uint32_t* r) {
    asm volatile("ldmatrix.sync.aligned.m8n8.x4.trans.shared.b16 {%0,%1,%2,%3}, [%4];"
                 : "=r"(r[0]), "=r"(r[1]), "=r"(r[2]), "=r"(r[3]) : "r"(addr));
}
__device__ __forceinline__ void ldmx2t(uint32_t addr, uint32_t* r) {
    asm volatile("ldmatrix.sync.aligned.m8n8.x2.trans.shared.b16 {%0,%1}, [%2];"
                 : "=r"(r[0]), "=r"(r[1]) : "r"(addr));
}
__device__ __forceinline__ void mma16816h(float* c, const uint32_t* a,
                                          uint32_t b0, uint32_t b1) {
    asm volatile(
        "mma.sync.aligned.m16n8k16.row.col.f32.f16.f16.f32 "
        "{%0,%1,%2,%3}, {%4,%5,%6,%7}, {%8,%9}, {%0,%1,%2,%3};"
        : "+f"(c[0]), "+f"(c[1]), "+f"(c[2]), "+f"(c[3])
        : "r"(a[0]), "r"(a[1]), "r"(a[2]), "r"(a[3]), "r"(b0), "r"(b1));
}
__device__ __forceinline__ float sqrt_approx(float x) {
    float y;
    asm("sqrt.approx.f32 %0, %1;" : "=f"(y) : "f"(x));
    return y;
}
__device__ __forceinline__ uint32_t h2pack(float a, float b) {
    const __half2 h = __floats2half2_rn(a, b);
    return *reinterpret_cast<const uint32_t*>(&h);
}

// ---------------------------------------------------------------------------
// x -> fp16 pre-convert
// ---------------------------------------------------------------------------
__global__ __launch_bounds__(256) void xhalf_kernel(const float* __restrict__ x) {
    const size_t i = (size_t)blockIdx.x * 1024 + threadIdx.x * 4;
    const float4 v = *reinterpret_cast<const float4*>(x + i);
    uint2 pk;
    pk.x = h2pack(v.x, v.y);
    pk.y = h2pack(v.z, v.w);
    *reinterpret_cast<uint2*>(&g_xh[i]) = pk;
}

// ---------------------------------------------------------------------------
// B prep: g_B[co][k*288+q*72+j] from weights/W_lrf/b_lrf.
// ---------------------------------------------------------------------------
__global__ __launch_bounds__(128) void bprep_kernel(
    const float* __restrict__ W,       // [15][256][256]
    const float* __restrict__ W_lrf,   // [36][32]
    const float* __restrict__ b_lrf)   // [32]
{
    extern __shared__ float s[];       // [64][256]
    __shared__ float Wl[36 * 32];
    __shared__ float bl[32];

    const int k   = blockIdx.x;
    const int q   = blockIdx.y;
    const int co  = blockIdx.z * 128 + threadIdx.x;
    const int tid = threadIdx.x;

    for (int i = tid; i < 36 * 32; i += 128) Wl[i] = W_lrf[i];
    if (tid < 32) bl[tid] = b_lrf[tid];

    const float* Wb = W + ((size_t)k * 256 + q * 64) * 256;
    for (int i = tid; i < 64 * 256 / 4; i += 128) {
        reinterpret_cast<float4*>(s)[i] =
            reinterpret_cast<const float4*>(Wb)[i];
    }
    __syncthreads();

    float acc[37];
    #pragma unroll
    for (int t = 0; t < 37; t++) acc[t] = 0.0f;

    #pragma unroll 4
    for (int c = 0; c < 32; c++) {
        const float sv = s[(32 + c) * 256 + co];
        #pragma unroll
        for (int t = 0; t < 36; t++) acc[t] += Wl[t * 32 + c] * sv;
        acc[36] += bl[c] * sv;
    }

    __half h[72];
    #pragma unroll
    for (int j = 0; j < 32; j++) h[j] = __float2half_rn(s[j * 256 + co]);
    #pragma unroll
    for (int t = 0; t < 37; t++) h[32 + t] = __float2half_rn(acc[t]);
    h[69] = __float2half_rn(0.f); h[70] = h[69]; h[71] = h[69];

    __half* dst = &g_B[(size_t)co * BIGK2 + k * KROW + q * QW];
    #pragma unroll
    for (int v = 0; v < 9; v++)
        reinterpret_cast<uint4*>(dst)[v] = reinterpret_cast<const uint4*>(h)[v];
}

// ---------------------------------------------------------------------------
// Stage 1: fp16 cp.async gather + geometry + tensor-core neighbor reduction.
// ---------------------------------------------------------------------------
__global__ __launch_bounds__(128) void stage1_kernel(
    const float* __restrict__ q_pts,
    const float* __restrict__ s_pts,
    const int*   __restrict__ neighb_inds,
    const float* __restrict__ q_lrf,
    const float* __restrict__ s_lrf,
    const float* __restrict__ kpts)
{
    __shared__ __align__(16) __half f_h[32 * LDF];      // 18944 B
    __shared__ __align__(16) __half w_h[4 * 16 * LDW];  // 5120 B
    __shared__ __align__(16) __half out_sm[15 * LDO];   // 8760 B
    __shared__ __align__(16) float  slrf_sm[30 * 36];   // 4320 B
    __shared__ __align__(16) float  spts_sm[30 * 4];
    __shared__ float ql[36];
    __shared__ float kp_s[48];
    __shared__ int   ind_s[30];
    __shared__ float qp[3];

    const int n    = blockIdx.x;
    const int tid  = threadIdx.x;
    const int wid  = tid >> 5;
    const int lane = tid & 31;

    if (tid < 36) ql[tid]    = q_lrf[(size_t)n * 36 + tid];
    if (tid < 45) kp_s[tid]  = kpts[tid];
    if (tid < 3)  qp[tid]    = q_pts[(size_t)n * 3 + tid];
    if (tid < 30) ind_s[tid] = neighb_inds[(size_t)n * NEI + tid];
    __syncthreads();   // ind_s ready

    const uint32_t slb = smem_u32(slrf_sm);
    const uint32_t spb = smem_u32(spts_sm);
    const uint32_t fba = smem_u32(f_h);
    const uint32_t wba = smem_u32(w_h);

    // ---- async gather: xh rows -> f_h[m][q*72 + c] fp16 (480 x 16B) ----
    #pragma unroll
    for (int it = 0; it < 4; it++) {
        const int i = tid + it * 128;
        if (i < 480) {
            const int m   = i >> 4;
            const int q   = (i >> 2) & 3;
            const int c8  = i & 3;
            const int ind = ind_s[m];
            const bool v  = (ind < S_SUP);
            cp16z(fba + (m * LDF + q * QW + c8 * 8) * 2,
                  g_xh + (size_t)(v ? ind : 0) * CIN_ + q * 32 + c8 * 8, v);
        }
    }
    // ---- async gather: s_lrf rows (270 x 16B) ----
    #pragma unroll
    for (int it = 0; it < 3; it++) {
        const int i = tid + it * 128;
        if (i < 270) {
            const int m = i / 9, t = i % 9;
            const int ind = ind_s[m];
            const bool v  = (ind < S_SUP);
            cp16z(slb + (m * 36 + t * 4) * 4,
                  s_lrf + (size_t)(v ? ind : 0) * 36 + t * 4, v);
        }
    }
    // ---- async gather: s_pts (3 x 4B per m) ----
    if (tid < 90) {
        const int m = tid / 3, e = tid % 3;
        const int ind = ind_s[m];
        const bool v  = (ind < S_SUP);
        cp4z(spb + (m * 4 + e) * 4, s_pts + (size_t)(v ? ind : 0) * 3 + e, v);
    }
    cp_commit();

    // ---- zero w_h and f_h pad rows while copies fly ----
    {
        uint4 z = make_uint4(0, 0, 0, 0);
        uint4* wz = reinterpret_cast<uint4*>(w_h);
        #pragma unroll
        for (int i = tid; i < 320; i += 128) wz[i] = z;
        uint4* fz = reinterpret_cast<uint4*>(f_h + 30 * LDF);
        if (tid < 74) fz[tid] = z;
    }
    cp_wait0();
    __syncthreads();

    // ---- per-(m,q) geometry -> w_h fp16 + f_h LRF channels fp16 ----
    if (tid < 120) {
        const int m = tid >> 2;
        const int q = tid & 3;
        const int ind = ind_s[m];
        const bool valid = (ind < S_SUP);
        const float* qlr = &ql[q * 9];

        const float nb0 = spts_sm[m * 4 + 0] - qp[0];
        const float nb1 = spts_sm[m * 4 + 1] - qp[1];
        const float nb2 = spts_sm[m * 4 + 2] - qp[2];
        const float a0 = nb0 * qlr[0] + nb1 * qlr[3] + nb2 * qlr[6];
        const float a1 = nb0 * qlr[1] + nb1 * qlr[4] + nb2 * qlr[7];
        const float a2 = nb0 * qlr[2] + nb1 * qlr[5] + nb2 * qlr[8];

        #pragma unroll
        for (int k = 0; k < KP; k++) {
            const float d0 = a0 - kp_s[k * 3 + 0];
            const float d1 = a1 - kp_s[k * 3 + 1];
            const float d2 = a2 - kp_s[k * 3 + 2];
            const float sq = d0 * d0 + d1 * d1 + d2 * d2;
            float w = 1.0f - sqrt_approx(sq) * INV_EXT;
            w = fmaxf(w, 0.0f);
            w_h[q * (16 * LDW) + k * LDW + m] = __float2half_rn(valid ? w : 0.0f);
        }

        float sl[36];
        {
            const float4* p = reinterpret_cast<const float4*>(&slrf_sm[m * 36]);
            #pragma unroll
            for (int t = 0; t < 9; t++) {
                const float4 v = p[t];
                sl[t * 4 + 0] = v.x; sl[t * 4 + 1] = v.y;
                sl[t * 4 + 2] = v.z; sl[t * 4 + 3] = v.w;
            }
        }
        float alv[36];
        #pragma unroll
        for (int s = 0; s < 4; s++)
            #pragma unroll
            for (int i = 0; i < 3; i++)
                #pragma unroll
                for (int j = 0; j < 3; j++) {
                    alv[s * 9 + i * 3 + j] =
                        qlr[0 * 3 + i] * sl[s * 9 + 0 * 3 + j] +
                        qlr[1 * 3 + i] * sl[s * 9 + 1 * 3 + j] +
                        qlr[2 * 3 + i] * sl[s * 9 + 2 * 3 + j];
                }
        uint32_t pk[20];
        #pragma unroll
        for (int i = 0; i < 18; i++) pk[i] = h2pack(alv[2 * i], alv[2 * i + 1]);
        pk[18] = h2pack(valid ? 1.0f : 0.0f, 0.0f);
        pk[19] = 0u;
        uint4* dst = reinterpret_cast<uint4*>(&f_h[m * LDF + q * QW + 32]);
        #pragma unroll
        for (int v = 0; v < 5; v++) {
            uint4 u;
            u.x = pk[4 * v + 0]; u.y = pk[4 * v + 1];
            u.z = pk[4 * v + 2]; u.w = pk[4 * v + 3];
            dst[v] = u;
        }
    }
    __syncthreads();

    // ---- phase 2 (tensor cores): per warp q = wid ----
    {
        const int q = wid;
        float c[9][4];
        #pragma unroll
        for (int t = 0; t < 9; t++)
            #pragma unroll
            for (int e = 0; e < 4; e++) c[t][e] = 0.0f;

        const uint32_t wb = wba + q * (16 * LDW) * 2;
        const int a_row = lane & 15;
        const int a_kof = (lane >> 4) * 8;
        const int b_row = (lane & 7) + ((lane >> 3) & 1) * 8;
        const int b_col = (lane >> 4) * 8;

        #pragma unroll
        for (int ks = 0; ks < 2; ks++) {
            const int k16 = ks * 16;
            uint32_t a[4];
            ldmx4(wb + (a_row * LDW + k16 + a_kof) * 2, a);

            uint32_t b[9][2];
            #pragma unroll
            for (int t = 0; t < 4; t++) {
                uint32_t r[4];
                ldmx4t(fba + ((k16 + b_row) * LDF + q * QW + t * 16 + b_col) * 2, r);
                b[2 * t + 0][0] = r[0]; b[2 * t + 0][1] = r[1];
                b[2 * t + 1][0] = r[2]; b[2 * t + 1][1] = r[3];
            }
            {
                uint32_t r[2];
                ldmx2t(fba + ((k16 + (lane & 15)) * LDF + q * QW + 64) * 2, r);
                b[8][0] = r[0]; b[8][1] = r[1];
            }

            #pragma unroll
            for (int t = 0; t < 9; t++)
                mma16816h(c[t], a, b[t][0], b[t][1]);
        }

        // ---- stage to out_sm [k][LDO], mask k=15 ----
        const int r1 = lane >> 2;
        const int jc = (lane & 3) * 2;
        __half* base = out_sm + r1 * LDO + q * QW + jc;
        #pragma unroll
        for (int t = 0; t < 9; t++) {
            const __half2 lo = __floats2half2_rn(c[t][0], c[t][1]);
            *reinterpret_cast<__half2*>(base + t * 8) = lo;
        }
        if (r1 < 7) {
            __half* base2 = base + 8 * LDO;
            #pragma unroll
            for (int t = 0; t < 9; t++) {
                const __half2 hi = __floats2half2_rn(c[t][2], c[t][3]);
                *reinterpret_cast<__half2*>(base2 + t * 8) = hi;
            }
        }
    }
    __syncthreads();

    // ---- coalesced copy out_sm -> g_A (1080 x uint2) ----
    {
        __half* dst = g_A + (size_t)n * BIGK2;
        #pragma unroll 3
        for (int i = tid; i < 15 * 72; i += 128) {
            const int k  = i / 72;
            const int jj = i % 72;
            const uint2 v = *reinterpret_cast<const uint2*>(&out_sm[k * LDO + jj * 4]);
            *reinterpret_cast<uint2*>(dst + k * KROW + jj * 4) = v;
        }
    }
}

// ---------------------------------------------------------------------------
// Stage 2: fp16 mma.sync GEMM. CTA 160x128, BK=48, 4 warps (80x64 tiles),
// 3-stage cp.async pipeline (two barriers/chunk, R12-proven structure).
// grid = 125 x 2 = 250 CTAs <= 296 capacity -> single wave.
// ---------------------------------------------------------------------------
__global__ __launch_bounds__(128)
void gemm_mma_kernel(const float* __restrict__ bias, float* __restrict__ C)
{
    extern __shared__ __align__(16) char sm[];
    const uint32_t s0 = smem_u32(sm);

    const int tid  = threadIdx.x;
    const int wid  = tid >> 5;
    const int lane = tid & 31;
    const int r0   = blockIdx.y * BM;
    const int c0   = blockIdx.x * BN;

    const int wm = (wid & 1) * 80;     // 2 warps in M (80 rows each)
    const int wn = (wid >> 1) * 64;    // 2 warps in N

    float acc[5][8][4];
    #pragma unroll
    for (int i = 0; i < 5; i++)
        #pragma unroll
        for (int j = 0; j < 8; j++)
            #pragma unroll
            for (int e = 0; e < 4; e++) acc[i][j][e] = 0.0f;

    auto load_chunk = [&](int c, int buf) {
        const int kc = c * BK;
        const uint32_t baseA = s0 + buf * BUF_BYTES;
        const uint32_t baseB = baseA + MATA_BYTES;
        // A: 160 rows x 6 chunks = 960 cp16
        #pragma unroll
        for (int it = 0; it < 8; it++) {
            const int i = tid + it * 128;
            if (i < 960) {
                const int row = i / 6;
                const int kq  = (i % 6) * 8;
                cp16(baseA + row * (LDS_ * 2) + kq * 2,
                     &g_A[(size_t)(r0 + row) * BIGK2 + kc + kq]);
            }
        }
        // B: 128 rows x 6 chunks = 768 cp16
        #pragma unroll
        for (int it = 0; it < 6; it++) {
            const int i = tid + it * 128;
            const int row = i / 6;
            const int kq  = (i % 6) * 8;
            cp16(baseB + row * (LDS_ * 2) + kq * 2,
                 &g_B[(size_t)(c0 + row) * BIGK2 + kc + kq]);
        }
        cp_commit();
    };

    const int a_row = lane & 15;
    const int a_kof = (lane >> 4) * 8;
    const int b_nof = ((lane >> 4) * 8) + (lane & 7);
    const int b_kof = ((lane >> 3) & 1) * 8;

    load_chunk(0, 0);

    for (int c = 0; c < NKC; c++) {
        const int buf = c % NSTAGE;
        if (c + 1 < NKC) { load_chunk(c + 1, (c + 1) % NSTAGE); cp_wait1(); }
        else             { cp_wait0(); }
        __syncthreads();

        const uint32_t bA = s0 + buf * BUF_BYTES;
        const uint32_t bB = bA + MATA_BYTES;

        #pragma unroll
        for (int ks = 0; ks < 3; ks++) {
            const int k16 = ks * 16;
            uint32_t bH[8][2];

            #pragma unroll
            for (int np = 0; np < 4; np++) {
                const uint32_t off =
                    (wn + np * 16 + b_nof) * (LDS_ * 2) + (k16 + b_kof) * 2;
                uint32_t t[4];
                ldmx4(bB + off, t);
                bH[np * 2 + 0][0] = t[0]; bH[np * 2 + 0][1] = t[1];
                bH[np * 2 + 1][0] = t[2]; bH[np * 2 + 1][1] = t[3];
            }

            // per-mt A fragment load keeps live registers low (acc is 160)
            #pragma unroll
            for (int mt = 0; mt < 5; mt++) {
                uint32_t aH[4];
                const uint32_t off =
                    (wm + mt * 16 + a_row) * (LDS_ * 2) + (k16 + a_kof) * 2;
                ldmx4(bA + off, aH);
                #pragma unroll
                for (int nt = 0; nt < 8; nt++)
                    mma16816h(acc[mt][nt], aH, bH[nt][0], bH[nt][1]);
            }
        }
        __syncthreads();   // required with 3-stage ring + pre-wait issue
    }

    const int erow = lane >> 2;
    const int ecol = (lane & 3) * 2;
    #pragma unroll
    for (int nt = 0; nt < 8; nt++) {
        const int col = c0 + wn + nt * 8 + ecol;
        const float b0 = bias[col], b1 = bias[col + 1];
        #pragma unroll
        for (int mt = 0; mt < 5; mt++) {
            #pragma unroll
            for (int h = 0; h < 2; h++) {
                const int row = r0 + wm + mt * 16 + erow + h * 8;
                if (row < N_Q) {
                    float v0 = acc[mt][nt][h * 2 + 0] + b0;
                    float v1 = acc[mt][nt][h * 2 + 1] + b1;
                    v0 = (v0 >= 0.f) ? v0 : 0.1f * v0;
                    v1 = (v1 >= 0.f) ? v1 : 0.1f * v1;
                    *reinterpret_cast<float2*>(&C[(size_t)row * COUT_ + col]) =
                        make_float2(v0, v1);
                }
            }
        }
    }
}

// ---------------------------------------------------------------------------
// Launch
// ---------------------------------------------------------------------------
extern "C" void kernel_launch(void* const* d_in, const int* in_sizes, int n_in,
                              void* d_out, int out_size) {
    const float* q_pts   = (const float*)d_in[0];
    const float* s_pts   = (const float*)d_in[1];
    const int*   inds    = (const int*)  d_in[2];
    const float* x       = (const float*)d_in[3];
    const float* q_lrf   = (const float*)d_in[4];
    const float* s_lrf   = (const float*)d_in[5];
    const float* kpts    = (const float*)d_in[6];
    const float* weights = (const float*)d_in[7];
    const float* W_lrf   = (const float*)d_in[8];
    const float* b_lrf   = (const float*)d_in[9];
    const float* bias    = (const float*)d_in[10];
    float* out = (float*)d_out;

    cudaFuncSetAttribute(bprep_kernel,
                         cudaFuncAttributeMaxDynamicSharedMemorySize, 65536);
    cudaFuncSetAttribute(gemm_mma_kernel,
                         cudaFuncAttributeMaxDynamicSharedMemorySize, SMEM_DYN);

    xhalf_kernel<<<(S_SUP * CIN_) / 1024, 256>>>(x);
    bprep_kernel<<<dim3(KP, 4, 2), 128, 65536>>>(weights, W_lrf, b_lrf);

    stage1_kernel<<<N_Q, 128>>>(q_pts, s_pts, inds, q_lrf, s_lrf, kpts);

    dim3 ggrid(COUT_ / BN, N_Q / BM);   // (2, 125) = 250 CTAs
    gemm_mma_kernel<<<ggrid, 128, SMEM_DYN>>>(bias, out);
}

// round 17
// speedup vs baseline: 1.1119x; 1.0569x over previous
#include <cuda_runtime.h>
#include <cuda_fp16.h>
#include <cstdint>
#include <math.h>

// ---------------------------------------------------------------------------
// Problem constants
// ---------------------------------------------------------------------------
namespace {
constexpr int N_Q   = 20000;
constexpr int S_SUP = 20000;
constexpr int NEI   = 30;
constexpr int KP    = 15;
constexpr int CIN_  = 128;
constexpr int COUT_ = 256;
constexpr float INV_EXT = 20.0f;

constexpr int M_PAD = 20096;        // stage1 scratch rows (>= N_Q)

// Extended-K layout: per k: 4 q-groups of 72 slots
constexpr int QW    = 72;
constexpr int KROW  = 4 * QW;             // 288
constexpr int BIGK2 = KP * KROW;          // 4320

// stage1 smem strides (halfs)
constexpr int LDF   = 296;   // f_h row stride: conflict-free
constexpr int LDW   = 40;    // w_h row stride
constexpr int LDO   = 292;   // out_sm row stride: conflict-free

// GEMM tiling: BM=160 -> grid 125x2 = 250 CTAs (single wave).
// Rows stored PACKED at 96B with chunk-rotation swizzle:
//   c' = (c + 3*((row>>2)&1)) mod 6   (c = 16B chunk index, 6 per row)
// -> every ldmatrix phase (8 consecutive rows, fixed c) hits 8 distinct banks.
constexpr int BM = 160, BN = 128, BK = 48;
constexpr int NKC = BIGK2 / BK;           // 90
constexpr int ROWB = 96;                  // packed row bytes (48 halfs)
constexpr int MATA_BYTES = BM * ROWB;     // 15360
constexpr int MATB_BYTES = BN * ROWB;     // 12288
constexpr int BUF_BYTES  = MATA_BYTES + MATB_BYTES;  // 27648
constexpr int NSTAGE = 4;                 // prefetch distance 2, ONE barrier
constexpr int SMEM_DYN  = NSTAGE * BUF_BYTES;        // 110592 -> 2 CTAs/SM
}

// ---------------------------------------------------------------------------
// Scratch (device globals, zero-initialized; pad rows never written)
// ---------------------------------------------------------------------------
__device__ __half g_A[(size_t)M_PAD * BIGK2];
__device__ __half g_B[(size_t)COUT_ * BIGK2];   // [co][kidx]
__device__ __half g_xh[(size_t)S_SUP * CIN_];   // x pre-converted to fp16

// ---------------------------------------------------------------------------
// PTX helpers (sm_80+/sm_100-family baseline; legal on family target)
// ---------------------------------------------------------------------------
__device__ __forceinline__ uint32_t smem_u32(const void* p) {
    uint32_t a;
    asm("{ .reg .u64 t; cvta.to.shared.u64 t, %1; cvt.u32.u64 %0, t; }"
        : "=r"(a) : "l"(p));
    return a;
}
__device__ __forceinline__ void cp16(uint32_t s, const void* g) {
    asm volatile("cp.async.cg.shared.global [%0], [%1], 16;" :: "r"(s), "l"(g));
}
__device__ __forceinline__ void cp16z(uint32_t s, const void* g, bool v) {
    const int sz = v ? 16 : 0;
    asm volatile("cp.async.cg.shared.global [%0], [%1], 16, %2;"
                 :: "r"(s), "l"(g), "r"(sz));
}
__device__ __forceinline__ void cp4z(uint32_t s, const void* g, bool v) {
    const int sz = v ? 4 : 0;
    asm volatile("cp.async.ca.shared.global [%0], [%1], 4, %2;"
                 :: "r"(s), "l"(g), "r"(sz));
}
__device__ __forceinline__ void cp_commit() {
    asm volatile("cp.async.commit_group;");
}
__device__ __forceinline__ void cp_wait2() {
    asm volatile("cp.async.wait_group 2;" ::: "memory");
}
__device__ __forceinline__ void cp_wait1() {
    asm volatile("cp.async.wait_group 1;" ::: "memory");
}
__device__ __forceinline__ void cp_wait0() {
    asm volatile("cp.async.wait_group 0;" ::: "memory");
}
__device__ __forceinline__ void ldmx4(uint32_t addr, uint32_t* r) {
    asm volatile("ldmatrix.sync.aligned.m8n8.x4.shared.b16 {%0,%1,%2,%3}, [%4];"
                 : "=r"(r[0]), "=r"(r[1]), "=r"(r[2]), "=r"(r[3]) : "r"(addr));
}
__device__ __forceinline__ void ldmx4t(uint32_t addr, uint32_t* r) {
    asm volatile("ldmatrix.sync.aligned.m8n8.x4.trans.shared.b16 {%0,%1,%2,%3}, [%4];"
                 : "=r"(r[0]), "=r"(r[1]), "=r"(r[2]), "=r"(r[3]) : "r"(addr));
}
__device__ __forceinline__ void ldmx2t(uint32_t addr, uint32_t* r) {
    asm volatile("ldmatrix.sync.aligned.m8n8.x2.trans.shared.b16 {%0,%1}, [%2];"
                 : "=r"(r[0]), "=r"(r[1]) : "r"(addr));
}
__device__ __forceinline__ void mma16816h(float* c, const uint32_t* a,
                                          uint32_t b0, uint32_t b1) {
    asm volatile(
        "mma.sync.aligned.m16n8k16.row.col.f32.f16.f16.f32 "
        "{%0,%1,%2,%3}, {%4,%5,%6,%7}, {%8,%9}, {%0,%1,%2,%3};"
        : "+f"(c[0]), "+f"(c[1]), "+f"(c[2]), "+f"(c[3])
        : "r"(a[0]), "r"(a[1]), "r"(a[2]), "r"(a[3]), "r"(b0), "r"(b1));
}
__device__ __forceinline__ float sqrt_approx(float x) {
    float y;
    asm("sqrt.approx.f32 %0, %1;" : "=f"(y) : "f"(x));
    return y;
}
__device__ __forceinline__ uint32_t h2pack(float a, float b) {
    const __half2 h = __floats2half2_rn(a, b);
    return *reinterpret_cast<const uint32_t*>(&h);
}
// packed-row swizzle: chunk c (0..5), row r -> byte offset within tile
__device__ __forceinline__ uint32_t swz_off(int row, int c) {
    int cc = c + 3 * ((row >> 2) & 1);
    cc -= (cc >= 6) ? 6 : 0;
    return (uint32_t)(row * ROWB + cc * 16);
}

// ---------------------------------------------------------------------------
// x -> fp16 pre-convert
// ---------------------------------------------------------------------------
__global__ __launch_bounds__(256) void xhalf_kernel(const float* __restrict__ x) {
    const size_t i = (size_t)blockIdx.x * 1024 + threadIdx.x * 4;
    const float4 v = *reinterpret_cast<const float4*>(x + i);
    uint2 pk;
    pk.x = h2pack(v.x, v.y);
    pk.y = h2pack(v.z, v.w);
    *reinterpret_cast<uint2*>(&g_xh[i]) = pk;
}

// ---------------------------------------------------------------------------
// B prep: g_B[co][k*288+q*72+j] from weights/W_lrf/b_lrf.
// ---------------------------------------------------------------------------
__global__ __launch_bounds__(128) void bprep_kernel(
    const float* __restrict__ W,       // [15][256][256]
    const float* __restrict__ W_lrf,   // [36][32]
    const float* __restrict__ b_lrf)   // [32]
{
    extern __shared__ float s[];       // [64][256]
    __shared__ float Wl[36 * 32];
    __shared__ float bl[32];

    const int k   = blockIdx.x;
    const int q   = blockIdx.y;
    const int co  = blockIdx.z * 128 + threadIdx.x;
    const int tid = threadIdx.x;

    for (int i = tid; i < 36 * 32; i += 128) Wl[i] = W_lrf[i];
    if (tid < 32) bl[tid] = b_lrf[tid];

    const float* Wb = W + ((size_t)k * 256 + q * 64) * 256;
    for (int i = tid; i < 64 * 256 / 4; i += 128) {
        reinterpret_cast<float4*>(s)[i] =
            reinterpret_cast<const float4*>(Wb)[i];
    }
    __syncthreads();

    float acc[37];
    #pragma unroll
    for (int t = 0; t < 37; t++) acc[t] = 0.0f;

    #pragma unroll 4
    for (int c = 0; c < 32; c++) {
        const float sv = s[(32 + c) * 256 + co];
        #pragma unroll
        for (int t = 0; t < 36; t++) acc[t] += Wl[t * 32 + c] * sv;
        acc[36] += bl[c] * sv;
    }

    __half h[72];
    #pragma unroll
    for (int j = 0; j < 32; j++) h[j] = __float2half_rn(s[j * 256 + co]);
    #pragma unroll
    for (int t = 0; t < 37; t++) h[32 + t] = __float2half_rn(acc[t]);
    h[69] = __float2half_rn(0.f); h[70] = h[69]; h[71] = h[69];

    __half* dst = &g_B[(size_t)co * BIGK2 + k * KROW + q * QW];
    #pragma unroll
    for (int v = 0; v < 9; v++)
        reinterpret_cast<uint4*>(dst)[v] = reinterpret_cast<const uint4*>(h)[v];
}

// ---------------------------------------------------------------------------
// Stage 1: fp16 cp.async gather + geometry + tensor-core neighbor reduction.
// ---------------------------------------------------------------------------
__global__ __launch_bounds__(128) void stage1_kernel(
    const float* __restrict__ q_pts,
    const float* __restrict__ s_pts,
    const int*   __restrict__ neighb_inds,
    const float* __restrict__ q_lrf,
    const float* __restrict__ s_lrf,
    const float* __restrict__ kpts)
{
    __shared__ __align__(16) __half f_h[32 * LDF];      // 18944 B
    __shared__ __align__(16) __half w_h[4 * 16 * LDW];  // 5120 B
    __shared__ __align__(16) __half out_sm[15 * LDO];   // 8760 B
    __shared__ __align__(16) float  slrf_sm[30 * 36];   // 4320 B
    __shared__ __align__(16) float  spts_sm[30 * 4];
    __shared__ float ql[36];
    __shared__ float kp_s[48];
    __shared__ int   ind_s[30];
    __shared__ float qp[3];

    const int n    = blockIdx.x;
    const int tid  = threadIdx.x;
    const int wid  = tid >> 5;
    const int lane = tid & 31;

    if (tid < 36) ql[tid]    = q_lrf[(size_t)n * 36 + tid];
    if (tid < 45) kp_s[tid]  = kpts[tid];
    if (tid < 3)  qp[tid]    = q_pts[(size_t)n * 3 + tid];
    if (tid < 30) ind_s[tid] = neighb_inds[(size_t)n * NEI + tid];
    __syncthreads();   // ind_s ready

    const uint32_t slb = smem_u32(slrf_sm);
    const uint32_t spb = smem_u32(spts_sm);
    const uint32_t fba = smem_u32(f_h);
    const uint32_t wba = smem_u32(w_h);

    // ---- async gather: xh rows -> f_h[m][q*72 + c] fp16 (480 x 16B) ----
    #pragma unroll
    for (int it = 0; it < 4; it++) {
        const int i = tid + it * 128;
        if (i < 480) {
            const int m   = i >> 4;
            const int q   = (i >> 2) & 3;
            const int c8  = i & 3;
            const int ind = ind_s[m];
            const bool v  = (ind < S_SUP);
            cp16z(fba + (m * LDF + q * QW + c8 * 8) * 2,
                  g_xh + (size_t)(v ? ind : 0) * CIN_ + q * 32 + c8 * 8, v);
        }
    }
    // ---- async gather: s_lrf rows (270 x 16B) ----
    #pragma unroll
    for (int it = 0; it < 3; it++) {
        const int i = tid + it * 128;
        if (i < 270) {
            const int m = i / 9, t = i % 9;
            const int ind = ind_s[m];
            const bool v  = (ind < S_SUP);
            cp16z(slb + (m * 36 + t * 4) * 4,
                  s_lrf + (size_t)(v ? ind : 0) * 36 + t * 4, v);
        }
    }
    // ---- async gather: s_pts (3 x 4B per m) ----
    if (tid < 90) {
        const int m = tid / 3, e = tid % 3;
        const int ind = ind_s[m];
        const bool v  = (ind < S_SUP);
        cp4z(spb + (m * 4 + e) * 4, s_pts + (size_t)(v ? ind : 0) * 3 + e, v);
    }
    cp_commit();

    // ---- zero w_h and f_h pad rows while copies fly ----
    {
        uint4 z = make_uint4(0, 0, 0, 0);
        uint4* wz = reinterpret_cast<uint4*>(w_h);
        #pragma unroll
        for (int i = tid; i < 320; i += 128) wz[i] = z;
        uint4* fz = reinterpret_cast<uint4*>(f_h + 30 * LDF);
        if (tid < 74) fz[tid] = z;
    }
    cp_wait0();
    __syncthreads();

    // ---- per-(m,q) geometry -> w_h fp16 + f_h LRF channels fp16 ----
    if (tid < 120) {
        const int m = tid >> 2;
        const int q = tid & 3;
        const int ind = ind_s[m];
        const bool valid = (ind < S_SUP);
        const float* qlr = &ql[q * 9];

        const float nb0 = spts_sm[m * 4 + 0] - qp[0];
        const float nb1 = spts_sm[m * 4 + 1] - qp[1];
        const float nb2 = spts_sm[m * 4 + 2] - qp[2];
        const float a0 = nb0 * qlr[0] + nb1 * qlr[3] + nb2 * qlr[6];
        const float a1 = nb0 * qlr[1] + nb1 * qlr[4] + nb2 * qlr[7];
        const float a2 = nb0 * qlr[2] + nb1 * qlr[5] + nb2 * qlr[8];

        #pragma unroll
        for (int k = 0; k < KP; k++) {
            const float d0 = a0 - kp_s[k * 3 + 0];
            const float d1 = a1 - kp_s[k * 3 + 1];
            const float d2 = a2 - kp_s[k * 3 + 2];
            const float sq = d0 * d0 + d1 * d1 + d2 * d2;
            float w = 1.0f - sqrt_approx(sq) * INV_EXT;
            w = fmaxf(w, 0.0f);
            w_h[q * (16 * LDW) + k * LDW + m] = __float2half_rn(valid ? w : 0.0f);
        }

        float sl[36];
        {
            const float4* p = reinterpret_cast<const float4*>(&slrf_sm[m * 36]);
            #pragma unroll
            for (int t = 0; t < 9; t++) {
                const float4 v = p[t];
                sl[t * 4 + 0] = v.x; sl[t * 4 + 1] = v.y;
                sl[t * 4 + 2] = v.z; sl[t * 4 + 3] = v.w;
            }
        }
        float alv[36];
        #pragma unroll
        for (int s = 0; s < 4; s++)
            #pragma unroll
            for (int i = 0; i < 3; i++)
                #pragma unroll
                for (int j = 0; j < 3; j++) {
                    alv[s * 9 + i * 3 + j] =
                        qlr[0 * 3 + i] * sl[s * 9 + 0 * 3 + j] +
                        qlr[1 * 3 + i] * sl[s * 9 + 1 * 3 + j] +
                        qlr[2 * 3 + i] * sl[s * 9 + 2 * 3 + j];
                }
        uint32_t pk[20];
        #pragma unroll
        for (int i = 0; i < 18; i++) pk[i] = h2pack(alv[2 * i], alv[2 * i + 1]);
        pk[18] = h2pack(valid ? 1.0f : 0.0f, 0.0f);
        pk[19] = 0u;
        uint4* dst = reinterpret_cast<uint4*>(&f_h[m * LDF + q * QW + 32]);
        #pragma unroll
        for (int v = 0; v < 5; v++) {
            uint4 u;
            u.x = pk[4 * v + 0]; u.y = pk[4 * v + 1];
            u.z = pk[4 * v + 2]; u.w = pk[4 * v + 3];
            dst[v] = u;
        }
    }
    __syncthreads();

    // ---- phase 2 (tensor cores): per warp q = wid ----
    {
        const int q = wid;
        float c[9][4];
        #pragma unroll
        for (int t = 0; t < 9; t++)
            #pragma unroll
            for (int e = 0; e < 4; e++) c[t][e] = 0.0f;

        const uint32_t wb = wba + q * (16 * LDW) * 2;
        const int a_row = lane & 15;
        const int a_kof = (lane >> 4) * 8;
        const int b_row = (lane & 7) + ((lane >> 3) & 1) * 8;
        const int b_col = (lane >> 4) * 8;

        #pragma unroll
        for (int ks = 0; ks < 2; ks++) {
            const int k16 = ks * 16;
            uint32_t a[4];
            ldmx4(wb + (a_row * LDW + k16 + a_kof) * 2, a);

            uint32_t b[9][2];
            #pragma unroll
            for (int t = 0; t < 4; t++) {
                uint32_t r[4];
                ldmx4t(fba + ((k16 + b_row) * LDF + q * QW + t * 16 + b_col) * 2, r);
                b[2 * t + 0][0] = r[0]; b[2 * t + 0][1] = r[1];
                b[2 * t + 1][0] = r[2]; b[2 * t + 1][1] = r[3];
            }
            {
                uint32_t r[2];
                ldmx2t(fba + ((k16 + (lane & 15)) * LDF + q * QW + 64) * 2, r);
                b[8][0] = r[0]; b[8][1] = r[1];
            }

            #pragma unroll
            for (int t = 0; t < 9; t++)
                mma16816h(c[t], a, b[t][0], b[t][1]);
        }

        // ---- stage to out_sm [k][LDO], mask k=15 ----
        const int r1 = lane >> 2;
        const int jc = (lane & 3) * 2;
        __half* base = out_sm + r1 * LDO + q * QW + jc;
        #pragma unroll
        for (int t = 0; t < 9; t++) {
            const __half2 lo = __floats2half2_rn(c[t][0], c[t][1]);
            *reinterpret_cast<__half2*>(base + t * 8) = lo;
        }
        if (r1 < 7) {
            __half* base2 = base + 8 * LDO;
            #pragma unroll
            for (int t = 0; t < 9; t++) {
                const __half2 hi = __floats2half2_rn(c[t][2], c[t][3]);
                *reinterpret_cast<__half2*>(base2 + t * 8) = hi;
            }
        }
    }
    __syncthreads();

    // ---- coalesced copy out_sm -> g_A (1080 x uint2) ----
    {
        __half* dst = g_A + (size_t)n * BIGK2;
        #pragma unroll 3
        for (int i = tid; i < 15 * 72; i += 128) {
            const int k  = i / 72;
            const int jj = i % 72;
            const uint2 v = *reinterpret_cast<const uint2*>(&out_sm[k * LDO + jj * 4]);
            *reinterpret_cast<uint2*>(dst + k * KROW + jj * 4) = v;
        }
    }
}

// ---------------------------------------------------------------------------
// Stage 2: fp16 mma.sync GEMM. CTA 160x128, BK=48, 4 warps (80x64 tiles).
// Packed 96B rows + chunk-rotation swizzle; 4-stage cp.async ring, prefetch
// distance 2, ONE barrier per chunk (writer (c+2)&3 is 3 buffers from the
// slowest reader (c-1)&3 -> race-free; proven structure from R14).
// grid = 2 x 125 = 250 CTAs, single wave, 2 CTAs/SM.
// ---------------------------------------------------------------------------
__global__ __launch_bounds__(128)
void gemm_mma_kernel(const float* __restrict__ bias, float* __restrict__ C)
{
    extern __shared__ __align__(16) char sm[];
    const uint32_t s0 = smem_u32(sm);

    const int tid  = threadIdx.x;
    const int wid  = tid >> 5;
    const int lane = tid & 31;
    const int r0   = blockIdx.y * BM;
    const int c0   = blockIdx.x * BN;

    const int wm = (wid & 1) * 80;
    const int wn = (wid >> 1) * 64;

    float acc[5][8][4];
    #pragma unroll
    for (int i = 0; i < 5; i++)
        #pragma unroll
        for (int j = 0; j < 8; j++)
            #pragma unroll
            for (int e = 0; e < 4; e++) acc[i][j][e] = 0.0f;

    auto load_chunk = [&](int c, int buf) {
        const int kc = c * BK;
        const uint32_t baseA = s0 + buf * BUF_BYTES;
        const uint32_t baseB = baseA + MATA_BYTES;
        // A: 160 rows x 6 chunks = 960 cp16 (swizzled dst)
        #pragma unroll
        for (int it = 0; it < 8; it++) {
            const int i = tid + it * 128;
            if (i < 960) {
                const int row = i / 6;
                const int cc  = i % 6;
                cp16(baseA + swz_off(row, cc),
                     &g_A[(size_t)(r0 + row) * BIGK2 + kc + cc * 8]);
            }
        }
        // B: 128 rows x 6 chunks = 768 cp16
        #pragma unroll
        for (int it = 0; it < 6; it++) {
            const int i = tid + it * 128;
            const int row = i / 6;
            const int cc  = i % 6;
            cp16(baseB + swz_off(row, cc),
                 &g_B[(size_t)(c0 + row) * BIGK2 + kc + cc * 8]);
        }
        cp_commit();
    };

    const int a_row = lane & 15;
    const int a_clo = (lane >> 4);               // A chunk low bit (a_kof/8)
    const int a_swz = 3 * ((a_row >> 2) & 1);    // per-thread rotation
    const int b_nof = ((lane >> 4) * 8) + (lane & 7);
    const int b_clo = ((lane >> 3) & 1);         // B chunk low bit
    const int b_swz = 3 * (((lane & 7) >> 2) & 1);

    load_chunk(0, 0);
    load_chunk(1, 1);

    for (int c = 0; c < NKC; c++) {
        if (c + 2 < NKC) { load_chunk(c + 2, (c + 2) & 3); cp_wait2(); }
        else if (c + 1 < NKC) { cp_wait1(); }
        else { cp_wait0(); }
        __syncthreads();     // single barrier per chunk

        const uint32_t bA = s0 + (c & 3) * BUF_BYTES;
        const uint32_t bB = bA + MATA_BYTES;

        #pragma unroll
        for (int ks = 0; ks < 3; ks++) {
            uint32_t bH[8][2];

            // B chunk index for this ks: cB = 2*ks + b_clo, rotated by b_swz
            int cB = 2 * ks + b_clo + b_swz;
            cB -= (cB >= 6) ? 6 : 0;
            #pragma unroll
            for (int np = 0; np < 4; np++) {
                const uint32_t off =
                    (uint32_t)((wn + np * 16 + b_nof) * ROWB + cB * 16);
                uint32_t t[4];
                ldmx4(bB + off, t);
                bH[np * 2 + 0][0] = t[0]; bH[np * 2 + 0][1] = t[1];
                bH[np * 2 + 1][0] = t[2]; bH[np * 2 + 1][1] = t[3];
            }

            // A chunk index: cA = 2*ks + a_clo, rotated by a_swz
            int cA = 2 * ks + a_clo + a_swz;
            cA -= (cA >= 6) ? 6 : 0;
            #pragma unroll
            for (int mt = 0; mt < 5; mt++) {
                uint32_t aH[4];
                const uint32_t off =
                    (uint32_t)((wm + mt * 16 + a_row) * ROWB + cA * 16);
                ldmx4(bA + off, aH);
                #pragma unroll
                for (int nt = 0; nt < 8; nt++)
                    mma16816h(acc[mt][nt], aH, bH[nt][0], bH[nt][1]);
            }
        }
        // no trailing barrier: 4-stage ring keeps the writer 3 buffers ahead
    }

    const int erow = lane >> 2;
    const int ecol = (lane & 3) * 2;
    #pragma unroll
    for (int nt = 0; nt < 8; nt++) {
        const int col = c0 + wn + nt * 8 + ecol;
        const float b0 = bias[col], b1 = bias[col + 1];
        #pragma unroll
        for (int mt = 0; mt < 5; mt++) {
            #pragma unroll
            for (int h = 0; h < 2; h++) {
                const int row = r0 + wm + mt * 16 + erow + h * 8;
                if (row < N_Q) {
                    float v0 = acc[mt][nt][h * 2 + 0] + b0;
                    float v1 = acc[mt][nt][h * 2 + 1] + b1;
                    v0 = (v0 >= 0.f) ? v0 : 0.1f * v0;
                    v1 = (v1 >= 0.f) ? v1 : 0.1f * v1;
                    *reinterpret_cast<float2*>(&C[(size_t)row * COUT_ + col]) =
                        make_float2(v0, v1);
                }
            }
        }
    }
}

// ---------------------------------------------------------------------------
// Launch
// ---------------------------------------------------------------------------
extern "C" void kernel_launch(void* const* d_in, const int* in_sizes, int n_in,
                              void* d_out, int out_size) {
    const float* q_pts   = (const float*)d_in[0];
    const float* s_pts   = (const float*)d_in[1];
    const int*   inds    = (const int*)  d_in[2];
    const float* x       = (const float*)d_in[3];
    const float* q_lrf   = (const float*)d_in[4];
    const float* s_lrf   = (const float*)d_in[5];
    const float* kpts    = (const float*)d_in[6];
    const float* weights = (const float*)d_in[7];
    const float* W_lrf   = (const float*)d_in[8];
    const float* b_lrf   = (const float*)d_in[9];
    const float* bias    = (const float*)d_in[10];
    float* out = (float*)d_out;

    cudaFuncSetAttribute(bprep_kernel,
                         cudaFuncAttributeMaxDynamicSharedMemorySize, 65536);
    cudaFuncSetAttribute(gemm_mma_kernel,
                         cudaFuncAttributeMaxDynamicSharedMemorySize, SMEM_DYN);

    xhalf_kernel<<<(S_SUP * CIN_) / 1024, 256>>>(x);
    bprep_kernel<<<dim3(KP, 4, 2), 128, 65536>>>(weights, W_lrf, b_lrf);

    stage1_kernel<<<N_Q, 128>>>(q_pts, s_pts, inds, q_lrf, s_lrf, kpts);

    dim3 ggrid(COUT_ / BN, N_Q / BM);   // (2, 125) = 250 CTAs
    gemm_mma_kernel<<<ggrid, 128, SMEM_DYN>>>(bias, out);
}